// round 6
// baseline (speedup 1.0000x reference)
#include <cuda_runtime.h>
#include <cuda_fp16.h>
#include <cstdint>

#define N_ROWS 8192
#define DIM    512
#define MARGIN 0.35f
#define KC     64                    // K elems per smem chunk (128B rows)
#define NCH    (DIM / KC)            // 8
#define TM     256                   // CTA tile rows (A)
#define TN     128                   // CTA tile cols (B)
#define NBI    (N_ROWS / TM)         // 32 row bands
#define NBJ    (N_ROWS / TN)         // 64 col tiles
#define ATILEB (TM * KC * 2)         // 32768
#define BTILEB (TN * KC * 2)         // 16384
#define STAGEB (ATILEB + BTILEB)     // 49152
#define NSTAGE 3
#define SMEMDYN (NSTAGE * STAGEB)    // 147456
#define NTILES 1056                  // sum_{i<32} (64 - 2i)

// ---------------- scratch (device globals; no allocation allowed) ----------
__device__ __align__(16) __half g_h[N_ROWS * DIM];
__device__ float    g_sq[N_ROWS];
__device__ float    g_ce[N_ROWS];
__device__ unsigned g_pos[N_ROWS];
__device__ unsigned g_neg[N_ROWS];
__device__ int      g_lab[N_ROWS];
__device__ unsigned g_done;          // zero-init; finalizer re-zeros for graph replay

// ---------------- float <-> monotone unsigned encoding ---------------------
__device__ __forceinline__ unsigned f2ord(float f) {
    unsigned u = __float_as_uint(f);
    return (u & 0x80000000u) ? ~u : (u | 0x80000000u);
}
__device__ __forceinline__ float ord2f(unsigned u) {
    unsigned b = (u & 0x80000000u) ? (u ^ 0x80000000u) : ~u;
    return __uint_as_float(b);
}
__device__ __forceinline__ float dev_inf() { return __int_as_float(0x7f800000); }

// ---------------- prep: norms, CE, fp16 cast, label detect, init -----------
__global__ void prep_kernel(const float* __restrict__ x, const void* __restrict__ labraw) {
    int row = blockIdx.x;
    int t   = threadIdx.x;          // 128 threads
    const float* xr = x + (size_t)row * DIM;

    // int64 labels in [0,512) -> every odd 32-bit word is zero (per-block vote).
    const int* raw32 = (const int*)labraw;
    int lab64 = !__syncthreads_or(raw32[2 * t + 1] != 0);

    float v[4];
#pragma unroll
    for (int i = 0; i < 4; i++) v[i] = xr[t + 128 * i];

    float ss = 0.f, mx = -dev_inf();
#pragma unroll
    for (int i = 0; i < 4; i++) { ss += v[i] * v[i]; mx = fmaxf(mx, v[i]); }
#pragma unroll
    for (int o = 16; o; o >>= 1) {
        ss += __shfl_xor_sync(0xffffffffu, ss, o);
        mx  = fmaxf(mx, __shfl_xor_sync(0xffffffffu, mx, o));
    }
    __shared__ float s_ss[4], s_mx[4], s_sq[4], s_se[4];
    int w = t >> 5, l = t & 31;
    if (l == 0) { s_ss[w] = ss; s_mx[w] = mx; }
    __syncthreads();
    ss = s_ss[0] + s_ss[1] + s_ss[2] + s_ss[3];
    mx = fmaxf(fmaxf(s_mx[0], s_mx[1]), fmaxf(s_mx[2], s_mx[3]));

    float norm = sqrtf(ss);
    float sq = 0.f, se = 0.f;
#pragma unroll
    for (int i = 0; i < 4; i++) {
        float xn = v[i] / norm;
        sq += xn * xn;
        se += expf(v[i] - mx);
    }
#pragma unroll
    for (int o = 16; o; o >>= 1) {
        sq += __shfl_xor_sync(0xffffffffu, sq, o);
        se += __shfl_xor_sync(0xffffffffu, se, o);
    }
    if (l == 0) { s_sq[w] = sq; s_se[w] = se; }
    __syncthreads();

    if (t == 0) {
        float sqt = s_sq[0] + s_sq[1] + s_sq[2] + s_sq[3];
        float set = s_se[0] + s_se[1] + s_se[2] + s_se[3];
        int lb = lab64 ? (int)((const long long*)labraw)[row]
                       : ((const int*)labraw)[row];
        g_sq[row]  = sqt;
        g_ce[row]  = mx + logf(set) - xr[lb];
        g_lab[row] = lb;
        g_pos[row] = f2ord(-dev_inf());
        g_neg[row] = f2ord(dev_inf());
    }

#pragma unroll
    for (int i = 0; i < 4; i++)
        g_h[(size_t)row * DIM + t + 128 * i] = __float2half_rn(v[i]);
}

// ---------------- mma helpers ----------------------------------------------
__device__ __forceinline__ void ldm_x4(uint32_t* d, uint32_t addr) {
    asm volatile("ldmatrix.sync.aligned.m8n8.x4.shared.b16 {%0,%1,%2,%3}, [%4];\n"
                 : "=r"(d[0]), "=r"(d[1]), "=r"(d[2]), "=r"(d[3]) : "r"(addr));
}
__device__ __forceinline__ void mma16816(float* c, const uint32_t* a, const uint32_t* b) {
    asm volatile(
        "mma.sync.aligned.m16n8k16.row.col.f32.f16.f16.f32 "
        "{%0,%1,%2,%3}, {%4,%5,%6,%7}, {%8,%9}, {%0,%1,%2,%3};\n"
        : "+f"(c[0]), "+f"(c[1]), "+f"(c[2]), "+f"(c[3])
        : "r"(a[0]), "r"(a[1]), "r"(a[2]), "r"(a[3]), "r"(b[0]), "r"(b[1]));
}
__device__ __forceinline__ void cpasync16(uint32_t dst, const void* src) {
    asm volatile("cp.async.cg.shared.global [%0], [%1], 16;" :: "r"(dst), "l"(src));
}

// swizzled 16B-chunk byte offset for (row r, logical chunk c), 128B rows
__device__ __forceinline__ uint32_t swz8(int r, int c) {
    return (uint32_t)((r * 8 + (c ^ (r & 7))) << 4);
}

// ---------------- fused triangular GEMM + masked max/min + finalize --------
__global__ void __launch_bounds__(256, 1) gemm_kernel(float* out) {
    extern __shared__ __align__(1024) char smdyn[];
    // map linear block -> coarse triangular tile: band i (256 rows), col j (128), j >= 2i
    // cum(i) = 64*i - i*(i-1)
    int b = blockIdx.x;
    int bi = 0;
    while (64 * (bi + 1) - (bi + 1) * bi <= b) bi++;
    int bj = 2 * bi + (b - (64 * bi - bi * (bi - 1)));

    const int tid  = threadIdx.x;
    const int lane = tid & 31, warp = tid >> 5;
    const int wm = warp & 3, wn = warp >> 2;   // 4x2 grid: warp tile 64 rows x 64 cols

    __shared__ float s_sqi[TM], s_sqj[TN];
    __shared__ int   s_li[TM], s_lj[TN];

    const int rowi0 = bi * TM, rowj0 = bj * TN;

    uint32_t smem0;
    asm("{ .reg .u64 t; cvta.to.shared.u64 t, %1; cvt.u32.u64 %0, t; }"
        : "=r"(smem0) : "l"(smdyn));

    auto issue_chunk = [&](int k, int stage) {
        const int kt = k * KC;
        const uint32_t sbA = smem0 + stage * STAGEB;
        const uint32_t sbB = sbA + ATILEB;
#pragma unroll
        for (int rep = 0; rep < 8; rep++) {           // A: 256 rows
            int q = rep * 256 + tid;
            int r = q >> 3, c = q & 7;
            cpasync16(sbA + swz8(r, c), g_h + (size_t)(rowi0 + r) * DIM + kt + c * 8);
        }
#pragma unroll
        for (int rep = 0; rep < 4; rep++) {           // B: 128 rows
            int q = rep * 256 + tid;
            int r = q >> 3, c = q & 7;
            cpasync16(sbB + swz8(r, c), g_h + (size_t)(rowj0 + r) * DIM + kt + c * 8);
        }
        asm volatile("cp.async.commit_group;" ::: "memory");
    };

    issue_chunk(0, 0);
    issue_chunk(1, 1);

    // per-tile metadata loads (256 threads)
    s_sqi[tid] = g_sq[rowi0 + tid];
    s_li[tid]  = g_lab[rowi0 + tid];
    if (tid < TN) { s_sqj[tid] = g_sq[rowj0 + tid]; s_lj[tid] = g_lab[rowj0 + tid]; }

    float acc[4][8][4];
#pragma unroll
    for (int mi = 0; mi < 4; mi++)
#pragma unroll
        for (int ni = 0; ni < 8; ni++)
#pragma unroll
            for (int k = 0; k < 4; k++) acc[mi][ni][k] = 0.f;

    const int m4 = lane >> 3, ri = lane & 7;

    for (int k = 0; k < NCH; k++) {
        if (k + 1 < NCH) asm volatile("cp.async.wait_group 1;" ::: "memory");
        else             asm volatile("cp.async.wait_group 0;" ::: "memory");
        __syncthreads();
        if (k + 2 < NCH) issue_chunk(k + 2, (k + 2) % NSTAGE);   // stage safe: last read in iter k-1

        const uint32_t baseA = smem0 + (k % NSTAGE) * STAGEB;
        const uint32_t baseB = baseA + ATILEB;

#pragma unroll
        for (int kk = 0; kk < 4; kk++) {
            uint32_t ah[4][4];
#pragma unroll
            for (int mi = 0; mi < 4; mi++) {
                int r = wm * 64 + mi * 16 + (m4 & 1) * 8 + ri;
                int c = kk * 2 + (m4 >> 1);
                ldm_x4(ah[mi], baseA + swz8(r, c));
            }
            uint32_t bh[4][4];
#pragma unroll
            for (int p4 = 0; p4 < 4; p4++) {
                int r = wn * 64 + p4 * 16 + (m4 >> 1) * 8 + ri;
                int c = kk * 2 + (m4 & 1);
                ldm_x4(bh[p4], baseB + swz8(r, c));
            }
#pragma unroll
            for (int mi = 0; mi < 4; mi++)
#pragma unroll
                for (int ni = 0; ni < 8; ni++)
                    mma16816(acc[mi][ni], ah[mi], &bh[ni >> 1][(ni & 1) * 2]);
        }
    }

    // ---------------- epilogue: dist + masked max/min reductions -----------
    const int g = lane >> 2, tg = lane & 3;
    const float NEG = -dev_inf(), POS = dev_inf();
    float cmx[16], cmn[16];
#pragma unroll
    for (int s = 0; s < 16; s++) { cmx[s] = NEG; cmn[s] = POS; }

#pragma unroll
    for (int mi = 0; mi < 4; mi++)
#pragma unroll
        for (int h = 0; h < 2; h++) {
            int li = wm * 64 + mi * 16 + h * 8 + g;
            int labi = s_li[li];
            float sqi = s_sqi[li];
            float rmax = NEG, rmin = POS;
#pragma unroll
            for (int ni = 0; ni < 8; ni++)
#pragma unroll
                for (int cc = 0; cc < 2; cc++) {
                    int lj = wn * 64 + ni * 8 + tg * 2 + cc;
                    float d = sqi + s_sqj[lj] - 2.0f * acc[mi][ni][h * 2 + cc];
                    int s = ni * 2 + cc;
                    if (labi == s_lj[lj]) {
                        rmax = fmaxf(rmax, d);
                        cmx[s] = fmaxf(cmx[s], d);
                    } else {
                        rmin = fminf(rmin, d);
                        cmn[s] = fminf(cmn[s], d);
                    }
                }
            // row reduction across tg (low 2 lane bits)
            rmax = fmaxf(rmax, __shfl_xor_sync(0xffffffffu, rmax, 1));
            rmax = fmaxf(rmax, __shfl_xor_sync(0xffffffffu, rmax, 2));
            rmin = fminf(rmin, __shfl_xor_sync(0xffffffffu, rmin, 1));
            rmin = fminf(rmin, __shfl_xor_sync(0xffffffffu, rmin, 2));
            if (tg == 0) {
                int grow = rowi0 + li;
                atomicMax(&g_pos[grow], f2ord(rmax));
                atomicMin(&g_neg[grow], f2ord(rmin));
            }
        }

    // column-side reduction (symmetry; idempotent so overlap double-count is fine)
#pragma unroll
    for (int s = 0; s < 16; s++) {
        float m_ = cmx[s], n_ = cmn[s];
        m_ = fmaxf(m_, __shfl_xor_sync(0xffffffffu, m_, 4));
        m_ = fmaxf(m_, __shfl_xor_sync(0xffffffffu, m_, 8));
        m_ = fmaxf(m_, __shfl_xor_sync(0xffffffffu, m_, 16));
        n_ = fminf(n_, __shfl_xor_sync(0xffffffffu, n_, 4));
        n_ = fminf(n_, __shfl_xor_sync(0xffffffffu, n_, 8));
        n_ = fminf(n_, __shfl_xor_sync(0xffffffffu, n_, 16));
        if (g == 0) {
            int gcol = rowj0 + wn * 64 + (s >> 1) * 8 + tg * 2 + (s & 1);
            atomicMax(&g_pos[gcol], f2ord(m_));
            atomicMin(&g_neg[gcol], f2ord(n_));
        }
    }

    // ---------------- last-block finalize (deterministic tree) -------------
    __shared__ unsigned s_last;
    __syncthreads();
    if (tid == 0) {
        __threadfence();
        s_last = (atomicAdd(&g_done, 1u) == (unsigned)(NTILES - 1));
    }
    __syncthreads();
    if (s_last) {
        __shared__ float sh[256];
        float ts = 0.f, cs = 0.f;
        for (int i = tid; i < N_ROWS; i += 256) {
            float p = ord2f(__ldcg(&g_pos[i]));
            float n = ord2f(__ldcg(&g_neg[i]));
            ts += fmaxf(p - n + MARGIN, 0.0f);
            cs += __ldcg(&g_ce[i]);
        }
        sh[tid] = ts; __syncthreads();
        for (int o = 128; o; o >>= 1) { if (tid < o) sh[tid] += sh[tid + o]; __syncthreads(); }
        float tt = sh[0]; __syncthreads();
        sh[tid] = cs; __syncthreads();
        for (int o = 128; o; o >>= 1) { if (tid < o) sh[tid] += sh[tid + o]; __syncthreads(); }
        if (tid == 0) {
            out[0] = tt / (float)N_ROWS + sh[0] / (float)N_ROWS;
            g_done = 0;
            __threadfence();
        }
    }
}

// ---------------- entry -----------------------------------------------------
extern "C" void kernel_launch(void* const* d_in, const int* in_sizes, int n_in,
                              void* d_out, int out_size) {
    const float* x   = (const float*)d_in[0];
    const void*  lab = d_in[1];

    cudaFuncSetAttribute(gemm_kernel, cudaFuncAttributeMaxDynamicSharedMemorySize, SMEMDYN);
    prep_kernel<<<N_ROWS, 128>>>(x, lab);
    gemm_kernel<<<NTILES, 256, SMEMDYN>>>((float*)d_out);
}

// round 7
// speedup vs baseline: 1.1241x; 1.1241x over previous
#include <cuda_runtime.h>
#include <cuda_fp16.h>
#include <cstdint>

#define N_ROWS 8192
#define DIM    512
#define BT     64            // 8192/128 tiles per dimension
#define MARGIN 0.35f
#define KC     64            // K elems per smem chunk (128B rows)
#define NCH    (DIM / KC)    // 8
#define TILEB  (128 * KC * 2)       // 16384 per operand tile
#define STAGEB (2 * TILEB)          // A + B = 32768
#define NSTAGE 3
#define SMEMDYN (NSTAGE * STAGEB)   // 98304
#define NTILES ((BT * (BT + 1)) / 2)

// ---------------- scratch (device globals; no allocation allowed) ----------
__device__ __align__(16) __half g_h[N_ROWS * DIM];
__device__ float    g_sq[N_ROWS];
__device__ float    g_ce[N_ROWS];
__device__ unsigned g_pos[N_ROWS];
__device__ unsigned g_neg[N_ROWS];
__device__ int      g_lab[N_ROWS];
__device__ unsigned g_done;          // zero-init; finalizer re-zeros for graph replay

// ---------------- float <-> monotone unsigned encoding ---------------------
__device__ __forceinline__ unsigned f2ord(float f) {
    unsigned u = __float_as_uint(f);
    return (u & 0x80000000u) ? ~u : (u | 0x80000000u);
}
__device__ __forceinline__ float ord2f(unsigned u) {
    unsigned b = (u & 0x80000000u) ? (u ^ 0x80000000u) : ~u;
    return __uint_as_float(b);
}
__device__ __forceinline__ float dev_inf() { return __int_as_float(0x7f800000); }

// ---------------- mbarrier helpers ------------------------------------------
#define MBAR_INIT(a, c) \
    asm volatile("mbarrier.init.shared.b64 [%0], %1;" :: "r"((uint32_t)(a)), "r"((uint32_t)(c)) : "memory")
#define MBAR_ARRIVE(a) \
    asm volatile("mbarrier.arrive.shared.b64 _, [%0];" :: "r"((uint32_t)(a)) : "memory")
#define CP_MBAR_ARRIVE(a) \
    asm volatile("cp.async.mbarrier.arrive.noinc.shared.b64 [%0];" :: "r"((uint32_t)(a)) : "memory")
#define MBAR_WAIT(a, ph) do {                                                          \
    uint32_t _m = (uint32_t)(a), _p = (uint32_t)(ph), _d;                              \
    asm volatile("{ .reg .pred p; mbarrier.try_wait.parity.acquire.cta.shared::cta.b64 p, [%1], %2;" \
                 " selp.b32 %0, 1, 0, p; }" : "=r"(_d) : "r"(_m), "r"(_p) : "memory"); \
    if (!_d) {                                                                         \
        asm volatile("{ .reg .pred P1; WL_%=: mbarrier.try_wait.parity.acquire.cta.shared::cta.b64 P1, [%0], %1, 0x989680;" \
                     " @P1 bra.uni WD_%=; bra.uni WL_%=; WD_%=: }" :: "r"(_m), "r"(_p) : "memory"); \
    } } while (0)

// ---------------- prep: norms, CE, fp16 cast, label detect, init -----------
__global__ void prep_kernel(const float* __restrict__ x, const void* __restrict__ labraw) {
    int row = blockIdx.x;
    int t   = threadIdx.x;          // 128 threads
    const float* xr = x + (size_t)row * DIM;

    // int64 labels in [0,512) -> every odd 32-bit word is zero (per-block vote).
    const int* raw32 = (const int*)labraw;
    int lab64 = !__syncthreads_or(raw32[2 * t + 1] != 0);

    float v[4];
#pragma unroll
    for (int i = 0; i < 4; i++) v[i] = xr[t + 128 * i];

    float ss = 0.f, mx = -dev_inf();
#pragma unroll
    for (int i = 0; i < 4; i++) { ss += v[i] * v[i]; mx = fmaxf(mx, v[i]); }
#pragma unroll
    for (int o = 16; o; o >>= 1) {
        ss += __shfl_xor_sync(0xffffffffu, ss, o);
        mx  = fmaxf(mx, __shfl_xor_sync(0xffffffffu, mx, o));
    }
    __shared__ float s_ss[4], s_mx[4], s_sq[4], s_se[4];
    int w = t >> 5, l = t & 31;
    if (l == 0) { s_ss[w] = ss; s_mx[w] = mx; }
    __syncthreads();
    ss = s_ss[0] + s_ss[1] + s_ss[2] + s_ss[3];
    mx = fmaxf(fmaxf(s_mx[0], s_mx[1]), fmaxf(s_mx[2], s_mx[3]));

    float norm = sqrtf(ss);
    float sq = 0.f, se = 0.f;
#pragma unroll
    for (int i = 0; i < 4; i++) {
        float xn = v[i] / norm;
        sq += xn * xn;
        se += expf(v[i] - mx);
    }
#pragma unroll
    for (int o = 16; o; o >>= 1) {
        sq += __shfl_xor_sync(0xffffffffu, sq, o);
        se += __shfl_xor_sync(0xffffffffu, se, o);
    }
    if (l == 0) { s_sq[w] = sq; s_se[w] = se; }
    __syncthreads();

    if (t == 0) {
        float sqt = s_sq[0] + s_sq[1] + s_sq[2] + s_sq[3];
        float set = s_se[0] + s_se[1] + s_se[2] + s_se[3];
        int lb = lab64 ? (int)((const long long*)labraw)[row]
                       : ((const int*)labraw)[row];
        g_sq[row]  = sqt;
        g_ce[row]  = mx + logf(set) - xr[lb];
        g_lab[row] = lb;
        g_pos[row] = f2ord(-dev_inf());
        g_neg[row] = f2ord(dev_inf());
    }

#pragma unroll
    for (int i = 0; i < 4; i++)
        g_h[(size_t)row * DIM + t + 128 * i] = __float2half_rn(v[i]);
}

// ---------------- mma helpers ----------------------------------------------
__device__ __forceinline__ void ldm_x4(uint32_t* d, uint32_t addr) {
    asm volatile("ldmatrix.sync.aligned.m8n8.x4.shared.b16 {%0,%1,%2,%3}, [%4];\n"
                 : "=r"(d[0]), "=r"(d[1]), "=r"(d[2]), "=r"(d[3]) : "r"(addr));
}
__device__ __forceinline__ void mma16816(float* c, const uint32_t* a, const uint32_t* b) {
    asm volatile(
        "mma.sync.aligned.m16n8k16.row.col.f32.f16.f16.f32 "
        "{%0,%1,%2,%3}, {%4,%5,%6,%7}, {%8,%9}, {%0,%1,%2,%3};\n"
        : "+f"(c[0]), "+f"(c[1]), "+f"(c[2]), "+f"(c[3])
        : "r"(a[0]), "r"(a[1]), "r"(a[2]), "r"(a[3]), "r"(b[0]), "r"(b[1]));
}
__device__ __forceinline__ void cpasync16(uint32_t dst, const void* src) {
    asm volatile("cp.async.cg.shared.global [%0], [%1], 16;" :: "r"(dst), "l"(src));
}

// swizzled 16B-chunk byte offset for (row r, logical chunk c) in 128x64 fp16 tile
__device__ __forceinline__ uint32_t swz8(int r, int c) {
    return (uint32_t)((r * 8 + (c ^ (r & 7))) << 4);
}

// ---------------- fused triangular GEMM + masked max/min + finalize --------
__global__ void __launch_bounds__(256, 2) gemm_kernel(float* out) {
    extern __shared__ __align__(1024) char smdyn[];
    __shared__ __align__(8) unsigned long long s_mbar[2 * NSTAGE]; // full[3], empty[3]
    __shared__ float s_sqi[128], s_sqj[128];
    __shared__ int   s_li[128], s_lj[128];

    // map linear block -> upper-triangular tile (bi <= bj)
    int b = blockIdx.x;
    int bi = 0;
    while ((bi + 1) * BT - ((bi + 1) * bi) / 2 <= b) bi++;
    int bj = bi + (b - (bi * BT - (bi * (bi - 1)) / 2));

    const int tid  = threadIdx.x;
    const int lane = tid & 31, warp = tid >> 5;
    const int wm = warp & 3, wn = warp >> 2;   // 4x2 warp grid: 32-row x 64-col per warp

    const int rowi0 = bi * 128, rowj0 = bj * 128;

    uint32_t smem0, mbar0;
    asm("{ .reg .u64 t; cvta.to.shared.u64 t, %1; cvt.u32.u64 %0, t; }"
        : "=r"(smem0) : "l"(smdyn));
    asm("{ .reg .u64 t; cvta.to.shared.u64 t, %1; cvt.u32.u64 %0, t; }"
        : "=r"(mbar0) : "l"(s_mbar));
    // full[s] = mbar0 + s*8 ; empty[s] = mbar0 + 24 + s*8

    if (tid == 0) {
#pragma unroll
        for (int s = 0; s < NSTAGE; s++) {
            MBAR_INIT(mbar0 + s * 8, 256);        // full: 256 cp-async arrives
            MBAR_INIT(mbar0 + 24 + s * 8, 256);   // empty: 256 thread arrives
        }
    }
    __syncthreads();

    auto issue_chunk = [&](int k, int stage) {
        const int kt = k * KC;
        const uint32_t sbA = smem0 + stage * STAGEB;
        const uint32_t sbB = sbA + TILEB;
#pragma unroll
        for (int rep = 0; rep < 4; rep++) {
            int q = rep * 256 + tid;            // 0..1023
            int r = q >> 3, c = q & 7;
            uint32_t so = swz8(r, c);
            size_t ga = (size_t)(rowi0 + r) * DIM + kt + c * 8;
            size_t gb = (size_t)(rowj0 + r) * DIM + kt + c * 8;
            cpasync16(sbA + so, g_h + ga);
            cpasync16(sbB + so, g_h + gb);
        }
        CP_MBAR_ARRIVE(mbar0 + stage * 8);
    };

    issue_chunk(0, 0);
    issue_chunk(1, 1);
    issue_chunk(2, 2);

    if (tid < 128) { s_sqi[tid] = g_sq[rowi0 + tid]; s_li[tid] = g_lab[rowi0 + tid]; }
    else { int t2 = tid - 128; s_sqj[t2] = g_sq[rowj0 + t2]; s_lj[t2] = g_lab[rowj0 + t2]; }

    float acc[2][8][4];
#pragma unroll
    for (int mi = 0; mi < 2; mi++)
#pragma unroll
        for (int ni = 0; ni < 8; ni++)
#pragma unroll
            for (int k = 0; k < 4; k++) acc[mi][ni][k] = 0.f;

    const int m4 = lane >> 3, ri = lane & 7;

    for (int k = 0; k < NCH; k++) {
        const int st = k % NSTAGE;
        const int ph = (k / NSTAGE) & 1;
        MBAR_WAIT(mbar0 + st * 8, ph);           // wait full

        const uint32_t baseA = smem0 + st * STAGEB;
        const uint32_t baseB = baseA + TILEB;

#pragma unroll
        for (int kk = 0; kk < 4; kk++) {
            uint32_t ah[2][4];
#pragma unroll
            for (int mi = 0; mi < 2; mi++) {
                int r = wm * 32 + mi * 16 + (m4 & 1) * 8 + ri;
                int c = kk * 2 + (m4 >> 1);
                ldm_x4(ah[mi], baseA + swz8(r, c));
            }
            uint32_t bh[4][4];
#pragma unroll
            for (int p4 = 0; p4 < 4; p4++) {
                int r = wn * 64 + p4 * 16 + (m4 >> 1) * 8 + ri;
                int c = kk * 2 + (m4 & 1);
                ldm_x4(bh[p4], baseB + swz8(r, c));
            }
#pragma unroll
            for (int mi = 0; mi < 2; mi++)
#pragma unroll
                for (int ni = 0; ni < 8; ni++)
                    mma16816(acc[mi][ni], ah[mi], &bh[ni >> 1][(ni & 1) * 2]);
        }

        MBAR_ARRIVE(mbar0 + 24 + st * 8);        // arrive empty (reads done)

        if (k + NSTAGE < NCH) {
            MBAR_WAIT(mbar0 + 24 + st * 8, ph);  // all threads done reading stage
            issue_chunk(k + NSTAGE, st);
        }
    }

    // ---------------- epilogue: dist + masked max/min reductions -----------
    const int g = lane >> 2, tg = lane & 3;
    const float NEG = -dev_inf(), POS = dev_inf();
    float rmax[2][2], rmin[2][2];
#pragma unroll
    for (int mi = 0; mi < 2; mi++)
#pragma unroll
        for (int h = 0; h < 2; h++) { rmax[mi][h] = NEG; rmin[mi][h] = POS; }
    float cmx[16], cmn[16];
#pragma unroll
    for (int s = 0; s < 16; s++) { cmx[s] = NEG; cmn[s] = POS; }

#pragma unroll
    for (int mi = 0; mi < 2; mi++)
#pragma unroll
        for (int h = 0; h < 2; h++) {
            int li = wm * 32 + mi * 16 + h * 8 + g;
            int labi = s_li[li];
            float sqi = s_sqi[li];
#pragma unroll
            for (int ni = 0; ni < 8; ni++)
#pragma unroll
                for (int cc = 0; cc < 2; cc++) {
                    int lj = wn * 64 + ni * 8 + tg * 2 + cc;
                    float d = sqi + s_sqj[lj] - 2.0f * acc[mi][ni][h * 2 + cc];
                    int s = ni * 2 + cc;
                    if (labi == s_lj[lj]) {
                        rmax[mi][h] = fmaxf(rmax[mi][h], d);
                        cmx[s] = fmaxf(cmx[s], d);
                    } else {
                        rmin[mi][h] = fminf(rmin[mi][h], d);
                        cmn[s] = fminf(cmn[s], d);
                    }
                }
        }

    // row reduction: lanes sharing g differ in tg (low 2 bits)
#pragma unroll
    for (int mi = 0; mi < 2; mi++)
#pragma unroll
        for (int h = 0; h < 2; h++) {
            float m_ = rmax[mi][h], n_ = rmin[mi][h];
            m_ = fmaxf(m_, __shfl_xor_sync(0xffffffffu, m_, 1));
            m_ = fmaxf(m_, __shfl_xor_sync(0xffffffffu, m_, 2));
            n_ = fminf(n_, __shfl_xor_sync(0xffffffffu, n_, 1));
            n_ = fminf(n_, __shfl_xor_sync(0xffffffffu, n_, 2));
            if (tg == 0) {
                int grow = rowi0 + wm * 32 + mi * 16 + h * 8 + g;
                atomicMax(&g_pos[grow], f2ord(m_));
                atomicMin(&g_neg[grow], f2ord(n_));
            }
        }

    // column reduction (symmetry): lanes sharing tg differ in g (bits 2..4)
    if (bi != bj) {
#pragma unroll
        for (int s = 0; s < 16; s++) {
            float m_ = cmx[s], n_ = cmn[s];
            m_ = fmaxf(m_, __shfl_xor_sync(0xffffffffu, m_, 4));
            m_ = fmaxf(m_, __shfl_xor_sync(0xffffffffu, m_, 8));
            m_ = fmaxf(m_, __shfl_xor_sync(0xffffffffu, m_, 16));
            n_ = fminf(n_, __shfl_xor_sync(0xffffffffu, n_, 4));
            n_ = fminf(n_, __shfl_xor_sync(0xffffffffu, n_, 8));
            n_ = fminf(n_, __shfl_xor_sync(0xffffffffu, n_, 16));
            if (g == 0) {
                int gcol = rowj0 + wn * 64 + (s >> 1) * 8 + tg * 2 + (s & 1);
                atomicMax(&g_pos[gcol], f2ord(m_));
                atomicMin(&g_neg[gcol], f2ord(n_));
            }
        }
    }

    // ---------------- last-block finalize (deterministic tree) -------------
    __shared__ unsigned s_last;
    __syncthreads();
    if (tid == 0) {
        __threadfence();
        s_last = (atomicAdd(&g_done, 1u) == (unsigned)(NTILES - 1));
    }
    __syncthreads();
    if (s_last) {
        __shared__ float sh[256];
        float ts = 0.f, cs = 0.f;
        for (int i = tid; i < N_ROWS; i += 256) {
            float p = ord2f(__ldcg(&g_pos[i]));
            float n = ord2f(__ldcg(&g_neg[i]));
            ts += fmaxf(p - n + MARGIN, 0.0f);
            cs += __ldcg(&g_ce[i]);
        }
        sh[tid] = ts; __syncthreads();
        for (int o = 128; o; o >>= 1) { if (tid < o) sh[tid] += sh[tid + o]; __syncthreads(); }
        float tt = sh[0]; __syncthreads();
        sh[tid] = cs; __syncthreads();
        for (int o = 128; o; o >>= 1) { if (tid < o) sh[tid] += sh[tid + o]; __syncthreads(); }
        if (tid == 0) {
            out[0] = tt / (float)N_ROWS + sh[0] / (float)N_ROWS;
            g_done = 0;
            __threadfence();
        }
    }
}

// ---------------- entry -----------------------------------------------------
extern "C" void kernel_launch(void* const* d_in, const int* in_sizes, int n_in,
                              void* d_out, int out_size) {
    const float* x   = (const float*)d_in[0];
    const void*  lab = d_in[1];

    cudaFuncSetAttribute(gemm_kernel, cudaFuncAttributeMaxDynamicSharedMemorySize, SMEMDYN);
    prep_kernel<<<N_ROWS, 128>>>(x, lab);
    gemm_kernel<<<NTILES, 256, SMEMDYN>>>((float*)d_out);
}